// round 1
// baseline (speedup 1.0000x reference)
#include <cuda_runtime.h>

#define OVERLAP_T 0.5f
#define VAR0 0.1f
#define VAR1 0.2f

#define BMAX 64
#define PMAX 32768
#define OMAX 64
#define NBLK (PMAX/256)

// Scratch (static device arrays; no allocation in kernel_launch)
__device__ float               g_ov[BMAX * PMAX];     // best_truth_overlap
__device__ int                 g_bti[BMAX * PMAX];    // best_truth_idx
__device__ float               g_ce[BMAX * PMAX];     // ce for negatives (0 at positives)
__device__ unsigned long long  g_key[BMAX * OMAX];    // per-(b,o) packed argmax key
__device__ int                 g_npos[BMAX];
__device__ float               g_pl[BMAX * NBLK];     // per-block smooth-L1 partials
__device__ float               g_pc[BMAX * NBLK];     // per-block pos-CE partials
__device__ float               g_cneg[BMAX];          // per-batch top-k negative CE sum

__global__ void k_zero(int B) {
    int i = blockIdx.x * blockDim.x + threadIdx.x;
    if (i < B * OMAX) g_key[i] = 0ull;
    if (i < B)        g_npos[i] = 0;
}

// ---------------------------------------------------------------------------
// Kernel A: per-prior best truth (max/argmax over O) + per-truth best prior
// (argmax over P via packed 64-bit keys).
// ---------------------------------------------------------------------------
__global__ __launch_bounds__(256)
void k_match(const float* __restrict__ priors,
             const float* __restrict__ targets,
             int P, int O) {
    int b   = blockIdx.y;
    int tid = threadIdx.x;
    int p   = blockIdx.x * blockDim.x + tid;

    __shared__ float4 tbox[OMAX];
    __shared__ float  tarea[OMAX];
    __shared__ unsigned long long skey[OMAX];

    if (tid < O) {
        const float* t = targets + ((long)b * O + tid) * 5;
        float4 v = make_float4(t[0], t[1], t[2], t[3]);
        tbox[tid]  = v;
        tarea[tid] = (v.z - v.x) * (v.w - v.y);
        skey[tid]  = 0ull;
    }
    __syncthreads();

    bool valid = (p < P);
    float px0 = 0.f, py0 = 0.f, px1 = 0.f, py1 = 0.f, parea = 0.f;
    if (valid) {
        float4 pr = reinterpret_cast<const float4*>(priors)[p];
        px0 = pr.x - pr.z * 0.5f;
        py0 = pr.y - pr.w * 0.5f;
        px1 = pr.x + pr.z * 0.5f;
        py1 = pr.y + pr.w * 0.5f;
        parea = (px1 - px0) * (py1 - py0);
    }

    float best = -1.0f;
    int   besto = 0;

    for (int o = 0; o < O; o++) {
        if (valid) {
            float4 t = tbox[o];
            float lx = fmaxf(t.x, px0), ly = fmaxf(t.y, py0);
            float rx = fminf(t.z, px1), ry = fminf(t.w, py1);
            float w = fmaxf(rx - lx, 0.0f), h = fmaxf(ry - ly, 0.0f);
            float inter = w * h;
            float iou = inter / (tarea[o] + parea - inter);
            if (iou > best) { best = iou; besto = o; }
            // key = (iou_bits << 32) | ~p  → max key = largest iou, ties to
            // smallest p (matches jnp.argmax first-occurrence).
            unsigned long long key =
                ((unsigned long long)__float_as_uint(iou) << 32) |
                (unsigned int)(~(unsigned int)p);
            // read-check to avoid most atomics (monotone: skip only if key
            // can never be the final max)
            if (key > skey[o]) atomicMax(&skey[o], key);
        }
    }
    if (valid) {
        long ip = (long)b * P + p;
        g_ov[ip]  = best;
        g_bti[ip] = besto;
    }
    __syncthreads();
    if (tid < O) atomicMax(&g_key[b * OMAX + tid], skey[tid]);
}

// ---------------------------------------------------------------------------
// Kernel B: force-match best prior per truth (sequential per batch, o
// ascending → last write wins on collisions, matching scatter semantics).
// ---------------------------------------------------------------------------
__global__ void k_scatter(int B, int P, int O) {
    int b = threadIdx.x;
    if (b >= B) return;
    for (int o = 0; o < O; o++) {
        unsigned long long key = g_key[b * OMAX + o];
        int p = (int)(~(unsigned int)(key & 0xffffffffull));
        long ip = (long)b * P + p;
        g_ov[ip]  = 2.0f;
        g_bti[ip] = o;
    }
}

// ---------------------------------------------------------------------------
// Kernel C: smooth-L1 (positives) + cross-entropy; emit ce_neg array and
// deterministic per-block partials.
// ---------------------------------------------------------------------------
__global__ __launch_bounds__(256)
void k_loss(const float* __restrict__ loc,
            const float* __restrict__ conf,
            const float* __restrict__ priors,
            const float* __restrict__ targets,
            int P, int O) {
    int b   = blockIdx.y;
    int tid = threadIdx.x;
    int p   = blockIdx.x * blockDim.x + tid;

    __shared__ float4 tbox[OMAX];
    if (tid < O) {
        const float* t = targets + ((long)b * O + tid) * 5;
        tbox[tid] = make_float4(t[0], t[1], t[2], t[3]);
    }
    __syncthreads();

    float ll = 0.0f, cpos = 0.0f;
    int   np = 0;

    if (p < P) {
        long ip = (long)b * P + p;
        float ov = g_ov[ip];
        int   o  = g_bti[ip];
        int   ct = (ov < OVERLAP_T) ? 0 : 1;

        float2 c = reinterpret_cast<const float2*>(conf)[ip];
        float mx = fmaxf(c.x, c.y);
        float mn = fminf(c.x, c.y);
        float lse = mx + log1pf(expf(mn - mx));
        float cgt = ct ? c.y : c.x;
        float ce  = lse - cgt;

        float ce_neg = ce;
        if (ct) {
            np = 1;
            cpos = ce;
            ce_neg = 0.0f;
            float4 pr = reinterpret_cast<const float4*>(priors)[p];
            float4 t  = tbox[o];
            float gcx = ((t.x + t.z) * 0.5f - pr.x) / (VAR0 * pr.z);
            float gcy = ((t.y + t.w) * 0.5f - pr.y) / (VAR0 * pr.w);
            float gw  = logf((t.z - t.x) / pr.z) / VAR1;
            float gh  = logf((t.w - t.y) / pr.w) / VAR1;
            float4 l = reinterpret_cast<const float4*>(loc)[ip];
            float d0 = l.x - gcx, d1 = l.y - gcy, d2 = l.z - gw, d3 = l.w - gh;
            float a0 = fabsf(d0), a1 = fabsf(d1), a2 = fabsf(d2), a3 = fabsf(d3);
            float s0 = (a0 < 1.0f) ? 0.5f * d0 * d0 : a0 - 0.5f;
            float s1 = (a1 < 1.0f) ? 0.5f * d1 * d1 : a1 - 0.5f;
            float s2 = (a2 < 1.0f) ? 0.5f * d2 * d2 : a2 - 0.5f;
            float s3 = (a3 < 1.0f) ? 0.5f * d3 * d3 : a3 - 0.5f;
            ll = (s0 + s1) + (s2 + s3);
        }
        g_ce[ip] = ce_neg;
    }

    __shared__ float sl[256], sc[256];
    __shared__ int   sn[256];
    sl[tid] = ll; sc[tid] = cpos; sn[tid] = np;
    __syncthreads();
    for (int s = 128; s; s >>= 1) {
        if (tid < s) { sl[tid] += sl[tid + s]; sc[tid] += sc[tid + s]; sn[tid] += sn[tid + s]; }
        __syncthreads();
    }
    if (tid == 0) {
        int bi = b * gridDim.x + blockIdx.x;
        g_pl[bi] = sl[0];
        g_pc[bi] = sc[0];
        atomicAdd(&g_npos[b], sn[0]);
    }
}

// ---------------------------------------------------------------------------
// Kernel D: radix select — sum of the k largest values of ce_neg per batch.
// 4 rounds of 8-bit MSB-first histogramming (positive floats order as uints).
// ---------------------------------------------------------------------------
__global__ __launch_bounds__(1024)
void k_topk(int P) {
    int b = blockIdx.x;
    const float* v = g_ce + (long)b * P;
    int tid = threadIdx.x;

    __shared__ unsigned int hist[256];
    __shared__ float        hsum[256];
    __shared__ unsigned int s_prefix, s_pmask;
    __shared__ int          s_krem, s_done;
    __shared__ float        s_sum;

    if (tid == 0) {
        int np = g_npos[b];
        int k = 3 * np;
        if (k > P - 1) k = P - 1;
        s_krem = k; s_prefix = 0u; s_pmask = 0u; s_sum = 0.0f;
        s_done = (k <= 0);
    }
    __syncthreads();
    if (s_done) { if (tid == 0) g_cneg[b] = 0.0f; return; }

    for (int r = 0; r < 4; r++) {
        int shift = 24 - 8 * r;
        for (int i = tid; i < 256; i += blockDim.x) { hist[i] = 0u; hsum[i] = 0.0f; }
        __syncthreads();
        unsigned int pmask = s_pmask, prefix = s_prefix;
        for (int i = tid; i < P; i += blockDim.x) {
            float f = v[i];
            unsigned int u = __float_as_uint(f);
            if ((u & pmask) == prefix) {
                unsigned int bin = (u >> shift) & 255u;
                atomicAdd(&hist[bin], 1u);
                atomicAdd(&hsum[bin], f);
            }
        }
        __syncthreads();
        if (tid == 0) {
            int krem = s_krem;
            float ss = s_sum;
            int cum = 0, chosen = 0;
            for (int bin = 255; bin >= 0; bin--) {
                int c = (int)hist[bin];
                if (cum + c < krem) { cum += c; ss += hsum[bin]; }
                else { chosen = bin; break; }
            }
            s_krem   = krem - cum;
            s_sum    = ss;
            s_prefix = prefix | ((unsigned int)chosen << shift);
            s_pmask  = pmask  | (255u << shift);
        }
        __syncthreads();
    }
    if (tid == 0) {
        float t = __uint_as_float(s_prefix);
        g_cneg[b] = s_sum + (float)s_krem * t;
    }
}

// ---------------------------------------------------------------------------
// Kernel E: deterministic final reduction → out[0]=loss_l/N, out[1]=loss_c/N
// ---------------------------------------------------------------------------
__global__ __launch_bounds__(256)
void k_final(float* __restrict__ out, int B, int nb) {
    __shared__ double sl[256], sc[256];
    __shared__ int    sn[256];
    int tid = threadIdx.x;
    double a = 0.0, c2 = 0.0;
    int n = 0;
    int tot = B * nb;
    for (int i = tid; i < tot; i += 256) { a += (double)g_pl[i]; c2 += (double)g_pc[i]; }
    for (int i = tid; i < B; i += 256)   { c2 += (double)g_cneg[i]; n += g_npos[i]; }
    sl[tid] = a; sc[tid] = c2; sn[tid] = n;
    __syncthreads();
    for (int s = 128; s; s >>= 1) {
        if (tid < s) { sl[tid] += sl[tid + s]; sc[tid] += sc[tid + s]; sn[tid] += sn[tid + s]; }
        __syncthreads();
    }
    if (tid == 0) {
        double N = (double)sn[0];
        if (N < 1.0) N = 1.0;
        out[0] = (float)(sl[0] / N);
        out[1] = (float)(sc[0] / N);
    }
}

extern "C" void kernel_launch(void* const* d_in, const int* in_sizes, int n_in,
                              void* d_out, int out_size) {
    const float* loc     = (const float*)d_in[0];
    const float* conf    = (const float*)d_in[1];
    const float* priors  = (const float*)d_in[2];
    const float* targets = (const float*)d_in[3];
    float* out = (float*)d_out;

    int P = in_sizes[2] / 4;
    int B = in_sizes[0] / (P * 4);
    int O = in_sizes[3] / (B * 5);
    int nb = (P + 255) / 256;

    k_zero<<<(B * OMAX + 255) / 256, 256>>>(B);

    dim3 grid(nb, B);
    k_match<<<grid, 256>>>(priors, targets, P, O);
    k_scatter<<<1, B>>>(B, P, O);
    k_loss<<<grid, 256>>>(loc, conf, priors, targets, P, O);
    k_topk<<<B, 1024>>>(P);
    k_final<<<1, 256>>>(out, B, nb);
}

// round 2
// speedup vs baseline: 3.0319x; 3.0319x over previous
#include <cuda_runtime.h>

#define OVERLAP_T 0.5f
#define VAR0 0.1f
#define VAR1 0.2f

#define BMAX 64
#define PMAX 32768
#define OMAX 64
#define NBLK (PMAX/256)

// Scratch (static device arrays; no allocation anywhere)
__device__ float               g_ce[BMAX * PMAX];     // ce for negatives (0 at positives)
__device__ unsigned long long  g_key[BMAX * OMAX];    // per-(b,o) packed best-prior key
__device__ int                 g_npos[BMAX];          // post-fixup num_pos per batch
__device__ float               g_pl[BMAX * NBLK];     // per-block smooth-L1 partials
__device__ float               g_pc[BMAX * NBLK];     // per-block pos-CE partials
__device__ int                 g_pn[BMAX * NBLK];     // per-block pos-count partials
__device__ float               g_fl[BMAX];            // fixup loc delta
__device__ float               g_fc[BMAX];            // fixup conf delta
__device__ float               g_cneg[BMAX];          // per-batch top-k negative CE sum

__global__ void k_zero(int B) {
    int i = blockIdx.x * blockDim.x + threadIdx.x;
    if (i < B * OMAX) g_key[i] = 0ull;
}

// IoU with fast reciprocal — must be bit-identical between k_main and k_fixup.
__device__ __forceinline__ float iou_one(float4 t, float ta,
                                         float px0, float py0, float px1, float py1,
                                         float pa) {
    float lx = fmaxf(t.x, px0), ly = fmaxf(t.y, py0);
    float rx = fminf(t.z, px1), ry = fminf(t.w, py1);
    float w = fmaxf(rx - lx, 0.0f), h = fmaxf(ry - ly, 0.0f);
    float inter = w * h;
    float den = ta + pa - inter;
    return __fdividef(inter, den);
}

// Smooth-L1 for prior p matched to truth box t (same formula in main & fixup).
__device__ __forceinline__ float sl1_of(float4 l, float4 pr, float4 t) {
    float gcx = ((t.x + t.z) * 0.5f - pr.x) / (VAR0 * pr.z);
    float gcy = ((t.y + t.w) * 0.5f - pr.y) / (VAR0 * pr.w);
    float gw  = __logf((t.z - t.x) / pr.z) * (1.0f / VAR1);
    float gh  = __logf((t.w - t.y) / pr.w) * (1.0f / VAR1);
    float d0 = l.x - gcx, d1 = l.y - gcy, d2 = l.z - gw, d3 = l.w - gh;
    float a0 = fabsf(d0), a1 = fabsf(d1), a2 = fabsf(d2), a3 = fabsf(d3);
    float s0 = (a0 < 1.0f) ? 0.5f * d0 * d0 : a0 - 0.5f;
    float s1 = (a1 < 1.0f) ? 0.5f * d1 * d1 : a1 - 0.5f;
    float s2 = (a2 < 1.0f) ? 0.5f * d2 * d2 : a2 - 0.5f;
    float s3 = (a3 < 1.0f) ? 0.5f * d3 * d3 : a3 - 0.5f;
    return (s0 + s1) + (s2 + s3);
}

__device__ __forceinline__ float lse2(float2 c) {
    float mx = fmaxf(c.x, c.y);
    float mn = fminf(c.x, c.y);
    return mx + log1pf(__expf(mn - mx));
}

// ---------------------------------------------------------------------------
// Fused match + loss. One thread per prior. Per-truth best prior found via
// warp shuffle reduction + one lane-0 smem atomic per (warp, truth).
// ---------------------------------------------------------------------------
__global__ __launch_bounds__(256)
void k_main(const float* __restrict__ loc,
            const float* __restrict__ conf,
            const float* __restrict__ priors,
            const float* __restrict__ targets,
            int P, int O) {
    int b    = blockIdx.y;
    int tid  = threadIdx.x;
    int lane = tid & 31;
    int p    = blockIdx.x * blockDim.x + tid;

    __shared__ float4 tb[OMAX];
    __shared__ float  ta_s[OMAX];
    __shared__ unsigned long long skey[OMAX];

    if (tid < O) {
        const float* t = targets + ((long)b * O + tid) * 5;
        float4 v = make_float4(t[0], t[1], t[2], t[3]);
        tb[tid]   = v;
        ta_s[tid] = (v.z - v.x) * (v.w - v.y);
        skey[tid] = 0ull;
    }
    __syncthreads();

    float4 pr = reinterpret_cast<const float4*>(priors)[p];
    float px0 = pr.x - pr.z * 0.5f;
    float py0 = pr.y - pr.w * 0.5f;
    float px1 = pr.x + pr.z * 0.5f;
    float py1 = pr.y + pr.w * 0.5f;
    float pa  = (px1 - px0) * (py1 - py0);

    float best = -1.0f;
    int   besto = 0;

    for (int o = 0; o < O; o++) {
        float iou = iou_one(tb[o], ta_s[o], px0, py0, px1, py1, pa);
        if (iou > best) { best = iou; besto = o; }

        // Warp-wide max + first-occurrence argmax (lowest lane = lowest p).
        float m = iou;
        #pragma unroll
        for (int off = 16; off; off >>= 1)
            m = fmaxf(m, __shfl_xor_sync(0xffffffffu, m, off));
        unsigned win = __ballot_sync(0xffffffffu, iou == m);
        if (lane == 0) {
            int src = __ffs(win) - 1;
            unsigned long long key =
                ((unsigned long long)__float_as_uint(m) << 32) |
                (unsigned int)(~(unsigned int)(p + src));
            if (key > skey[o]) atomicMax(&skey[o], key);
        }
    }

    // ----- loss stage (pre-forced-match; fixup adjusts the ~B*O forced) -----
    long ip = (long)b * P + p;
    int ct = (best >= OVERLAP_T) ? 1 : 0;

    float2 c = reinterpret_cast<const float2*>(conf)[ip];
    float lse = lse2(c);

    float ll = 0.0f, cp = 0.0f, ce_neg;
    int np = 0;
    if (ct) {
        np = 1;
        cp = lse - c.y;
        ce_neg = 0.0f;
        float4 l = reinterpret_cast<const float4*>(loc)[ip];
        ll = sl1_of(l, pr, tb[besto]);
    } else {
        ce_neg = lse - c.x;
    }
    g_ce[ip] = ce_neg;

    __shared__ float sl[256], sc[256];
    __shared__ int   sn[256];
    sl[tid] = ll; sc[tid] = cp; sn[tid] = np;
    __syncthreads();
    for (int s = 128; s; s >>= 1) {
        if (tid < s) { sl[tid] += sl[tid + s]; sc[tid] += sc[tid + s]; sn[tid] += sn[tid + s]; }
        __syncthreads();
    }
    if (tid == 0) {
        int bi = b * gridDim.x + blockIdx.x;
        g_pl[bi] = sl[0];
        g_pc[bi] = sc[0];
        g_pn[bi] = sn[0];
    }
    if (tid < O) atomicMax(&g_key[b * OMAX + tid], skey[tid]);
}

// ---------------------------------------------------------------------------
// Fixup: apply forced matches as deltas (last-wins on duplicate priors),
// finalize per-batch num_pos.
// ---------------------------------------------------------------------------
__global__ void k_fixup(const float* __restrict__ loc,
                        const float* __restrict__ conf,
                        const float* __restrict__ priors,
                        const float* __restrict__ targets,
                        int B, int P, int O, int nb) {
    int b = threadIdx.x;
    if (b >= B) return;

    int np = 0;
    for (int j = 0; j < nb; j++) np += g_pn[b * nb + j];

    int ps[OMAX];
    for (int o = 0; o < O; o++)
        ps[o] = (int)(~(unsigned int)(g_key[b * OMAX + o] & 0xffffffffull));

    float dl = 0.0f, dc = 0.0f;
    int dn = 0;

    for (int o = 0; o < O; o++) {
        int p = ps[o];
        bool dup = false;
        for (int o2 = o + 1; o2 < O; o2++) if (ps[o2] == p) dup = true;
        if (dup) continue;  // last-wins scatter semantics

        float4 pr = reinterpret_cast<const float4*>(priors)[p];
        float px0 = pr.x - pr.z * 0.5f;
        float py0 = pr.y - pr.w * 0.5f;
        float px1 = pr.x + pr.z * 0.5f;
        float py1 = pr.y + pr.w * 0.5f;
        float pa  = (px1 - px0) * (py1 - py0);

        // recompute this prior's original (pre-force) match — identical formula
        float best = -1.0f; int bo = 0;
        for (int oo = 0; oo < O; oo++) {
            const float* tt = targets + ((long)b * O + oo) * 5;
            float4 t = make_float4(tt[0], tt[1], tt[2], tt[3]);
            float ta = (t.z - t.x) * (t.w - t.y);
            float iou = iou_one(t, ta, px0, py0, px1, py1, pa);
            if (iou > best) { best = iou; bo = oo; }
        }
        int ct = (best >= OVERLAP_T) ? 1 : 0;

        long ip = (long)b * P + p;
        float4 l = reinterpret_cast<const float4*>(loc)[ip];
        const float* tf = targets + ((long)b * O + o) * 5;
        float4 tnew = make_float4(tf[0], tf[1], tf[2], tf[3]);
        float sl_new = sl1_of(l, pr, tnew);

        if (ct) {
            const float* to = targets + ((long)b * O + bo) * 5;
            float4 told = make_float4(to[0], to[1], to[2], to[3]);
            dl += sl_new - sl1_of(l, pr, told);
            // conf target unchanged (1→1): no dc/dn delta
        } else {
            float2 c = reinterpret_cast<const float2*>(conf)[ip];
            float lse = lse2(c);
            dl += sl_new;
            dc += (lse - c.y);   // becomes positive CE
            dn += 1;
            g_ce[ip] = 0.0f;     // remove from negative pool
        }
    }
    g_npos[b] = np + dn;
    g_fl[b] = dl;
    g_fc[b] = dc;
}

// ---------------------------------------------------------------------------
// Top-k sum of negative CE per batch: 4 count-only radix rounds with
// warp-aggregated histogram, then one strictly-greater sum pass.
// ---------------------------------------------------------------------------
__global__ __launch_bounds__(1024)
void k_topk(int P) {
    int b = blockIdx.x;
    const float* v = g_ce + (long)b * P;
    int tid  = threadIdx.x;
    int lane = tid & 31;

    __shared__ unsigned int hist[256];
    __shared__ unsigned int s_prefix, s_pmask;
    __shared__ int s_krem;

    if (tid == 0) {
        int k = 3 * g_npos[b];
        if (k > P - 1) k = P - 1;
        s_krem = k; s_prefix = 0u; s_pmask = 0u;
    }
    __syncthreads();
    int k0 = s_krem;
    if (k0 <= 0) { if (tid == 0) g_cneg[b] = 0.0f; return; }

    for (int r = 0; r < 4; r++) {
        int shift = 24 - 8 * r;
        if (tid < 256) hist[tid] = 0u;
        __syncthreads();
        unsigned int pmask = s_pmask, prefix = s_prefix;
        for (int i = tid; i < P; i += 1024) {
            unsigned int u = __float_as_uint(v[i]);
            if ((u & pmask) == prefix) {
                unsigned int bin = (u >> shift) & 255u;
                unsigned grp = __match_any_sync(__activemask(), bin);
                if (lane == __ffs(grp) - 1)
                    atomicAdd(&hist[bin], (unsigned)__popc(grp));
            }
        }
        __syncthreads();
        if (tid == 0) {
            int krem = s_krem;
            int cum = 0, chosen = 0;
            for (int bin = 255; bin >= 0; bin--) {
                int c = (int)hist[bin];
                if (cum + c < krem) cum += c;
                else { chosen = bin; break; }
            }
            s_krem   = krem - cum;
            s_prefix = prefix | ((unsigned int)chosen << shift);
            s_pmask  = pmask  | (255u << shift);
        }
        __syncthreads();
    }

    unsigned int tbits = s_prefix;
    float t = __uint_as_float(tbits);
    float acc = 0.0f;
    for (int i = tid; i < P; i += 1024) {
        float f = v[i];
        if (__float_as_uint(f) > tbits) acc += f;
    }
    __shared__ float ssum[1024];
    ssum[tid] = acc;
    __syncthreads();
    for (int s = 512; s; s >>= 1) {
        if (tid < s) ssum[tid] += ssum[tid + s];
        __syncthreads();
    }
    if (tid == 0) g_cneg[b] = ssum[0] + (float)s_krem * t;
}

// ---------------------------------------------------------------------------
// Final reduction → out[0]=loss_l/N, out[1]=loss_c/N
// ---------------------------------------------------------------------------
__global__ __launch_bounds__(256)
void k_final(float* __restrict__ out, int B, int nb) {
    __shared__ double sl[256], sc[256];
    __shared__ int    sn[256];
    int tid = threadIdx.x;
    double a = 0.0, c2 = 0.0;
    int n = 0;
    int tot = B * nb;
    for (int i = tid; i < tot; i += 256) { a += (double)g_pl[i]; c2 += (double)g_pc[i]; }
    for (int i = tid; i < B; i += 256) {
        a  += (double)g_fl[i];
        c2 += (double)g_fc[i] + (double)g_cneg[i];
        n  += g_npos[i];
    }
    sl[tid] = a; sc[tid] = c2; sn[tid] = n;
    __syncthreads();
    for (int s = 128; s; s >>= 1) {
        if (tid < s) { sl[tid] += sl[tid + s]; sc[tid] += sc[tid + s]; sn[tid] += sn[tid + s]; }
        __syncthreads();
    }
    if (tid == 0) {
        double N = (double)sn[0];
        if (N < 1.0) N = 1.0;
        out[0] = (float)(sl[0] / N);
        out[1] = (float)(sc[0] / N);
    }
}

extern "C" void kernel_launch(void* const* d_in, const int* in_sizes, int n_in,
                              void* d_out, int out_size) {
    const float* loc     = (const float*)d_in[0];
    const float* conf    = (const float*)d_in[1];
    const float* priors  = (const float*)d_in[2];
    const float* targets = (const float*)d_in[3];
    float* out = (float*)d_out;

    int P = in_sizes[2] / 4;
    int B = in_sizes[0] / (P * 4);
    int O = in_sizes[3] / (B * 5);
    int nb = (P + 255) / 256;

    k_zero<<<(B * OMAX + 255) / 256, 256>>>(B);

    dim3 grid(nb, B);
    k_main<<<grid, 256>>>(loc, conf, priors, targets, P, O);
    k_fixup<<<1, B>>>(loc, conf, priors, targets, B, P, O, nb);
    k_topk<<<B, 1024>>>(P);
    k_final<<<1, 256>>>(out, B, nb);
}

// round 3
// speedup vs baseline: 4.6005x; 1.5174x over previous
#include <cuda_runtime.h>

#define OVERLAP_T 0.5f
#define VAR0 0.1f
#define VAR1 0.2f

#define BMAX 64
#define PMAX 32768
#define OMAX 64
#define NBLK (PMAX/256)

// Scratch (static device arrays; no allocation anywhere)
__device__ float               g_ce[BMAX * PMAX];     // ce for negatives (0 at positives)
__device__ unsigned long long  g_key[BMAX * OMAX];    // per-(b,o) packed best-prior key
__device__ int                 g_npos[BMAX];          // post-fixup num_pos per batch
__device__ float               g_pl[BMAX * NBLK];     // per-block smooth-L1 partials
__device__ float               g_pc[BMAX * NBLK];     // per-block pos-CE partials
__device__ int                 g_pn[BMAX * NBLK];     // per-block pos-count partials
__device__ float               g_fl[BMAX];            // fixup loc delta
__device__ float               g_fc[BMAX];            // fixup conf delta
__device__ float               g_cneg[BMAX];          // per-batch top-k negative CE sum

__global__ void k_zero(int B) {
    int i = blockIdx.x * blockDim.x + threadIdx.x;
    if (i < B * OMAX) g_key[i] = 0ull;
}

// IoU with fast reciprocal — identical between k_main and k_fixup.
__device__ __forceinline__ float iou_one(float4 t, float ta,
                                         float px0, float py0, float px1, float py1,
                                         float pa) {
    float lx = fmaxf(t.x, px0), ly = fmaxf(t.y, py0);
    float rx = fminf(t.z, px1), ry = fminf(t.w, py1);
    float w = fmaxf(rx - lx, 0.0f), h = fmaxf(ry - ly, 0.0f);
    float inter = w * h;
    float den = ta + pa - inter;
    return __fdividef(inter, den);
}

__device__ __forceinline__ float sl1_of(float4 l, float4 pr, float4 t) {
    float gcx = ((t.x + t.z) * 0.5f - pr.x) / (VAR0 * pr.z);
    float gcy = ((t.y + t.w) * 0.5f - pr.y) / (VAR0 * pr.w);
    float gw  = __logf((t.z - t.x) / pr.z) * (1.0f / VAR1);
    float gh  = __logf((t.w - t.y) / pr.w) * (1.0f / VAR1);
    float d0 = l.x - gcx, d1 = l.y - gcy, d2 = l.z - gw, d3 = l.w - gh;
    float a0 = fabsf(d0), a1 = fabsf(d1), a2 = fabsf(d2), a3 = fabsf(d3);
    float s0 = (a0 < 1.0f) ? 0.5f * d0 * d0 : a0 - 0.5f;
    float s1 = (a1 < 1.0f) ? 0.5f * d1 * d1 : a1 - 0.5f;
    float s2 = (a2 < 1.0f) ? 0.5f * d2 * d2 : a2 - 0.5f;
    float s3 = (a3 < 1.0f) ? 0.5f * d3 * d3 : a3 - 0.5f;
    return (s0 + s1) + (s2 + s3);
}

__device__ __forceinline__ float lse2(float2 c) {
    float mx = fmaxf(c.x, c.y);
    float mn = fminf(c.x, c.y);
    return mx + __logf(1.0f + __expf(mn - mx));
}

// ---------------------------------------------------------------------------
// Fused match + loss with per-truth early-out filter.
// ---------------------------------------------------------------------------
__global__ __launch_bounds__(256)
void k_main(const float* __restrict__ loc,
            const float* __restrict__ conf,
            const float* __restrict__ priors,
            const float* __restrict__ targets,
            int P, int O) {
    int b    = blockIdx.y;
    int tid  = threadIdx.x;
    int lane = tid & 31;
    int p    = blockIdx.x * blockDim.x + tid;

    __shared__ float4 tb[OMAX];
    __shared__ float  ta_s[OMAX];
    __shared__ unsigned long long skey[OMAX];

    if (tid < O) {
        const float* t = targets + ((long)b * O + tid) * 5;
        float4 v = make_float4(t[0], t[1], t[2], t[3]);
        tb[tid]   = v;
        ta_s[tid] = (v.z - v.x) * (v.w - v.y);
        skey[tid] = 0ull;
    }
    __syncthreads();

    float4 pr = reinterpret_cast<const float4*>(priors)[p];
    float px0 = pr.x - pr.z * 0.5f;
    float py0 = pr.y - pr.w * 0.5f;
    float px1 = pr.x + pr.z * 0.5f;
    float py1 = pr.y + pr.w * 0.5f;
    float pa  = (px1 - px0) * (py1 - py0);

    float best = -1.0f;
    int   besto = 0;

    const unsigned* skey_hi = reinterpret_cast<const unsigned*>(skey);

    for (int o = 0; o < O; o++) {
        float iou = iou_one(tb[o], ta_s[o], px0, py0, px1, py1, pa);
        if (iou > best) { best = iou; besto = o; }

        // Early-out: only do the expensive reduction if some lane could still
        // improve (>= keeps equal-iou candidates for the lowest-index tiebreak;
        // atomicMax below guards all races — filter is monotone-safe).
        unsigned ib = __float_as_uint(iou);
        if (__any_sync(0xffffffffu, ib >= skey_hi[2 * o + 1])) {
            float m = iou;
            #pragma unroll
            for (int off = 16; off; off >>= 1)
                m = fmaxf(m, __shfl_xor_sync(0xffffffffu, m, off));
            unsigned win = __ballot_sync(0xffffffffu, iou == m);
            if (lane == 0) {
                int src = __ffs(win) - 1;
                unsigned long long key =
                    ((unsigned long long)__float_as_uint(m) << 32) |
                    (unsigned int)(~(unsigned int)(p + src));
                if (key > skey[o]) atomicMax(&skey[o], key);
            }
        }
    }

    // ----- loss stage (pre-forced-match; fixup adjusts the forced priors) ---
    long ip = (long)b * P + p;
    int ct = (best >= OVERLAP_T) ? 1 : 0;

    float2 c = reinterpret_cast<const float2*>(conf)[ip];
    float lse = lse2(c);

    float ll = 0.0f, cp = 0.0f, ce_neg;
    int np = 0;
    if (ct) {
        np = 1;
        cp = lse - c.y;
        ce_neg = 0.0f;
        float4 l = reinterpret_cast<const float4*>(loc)[ip];
        ll = sl1_of(l, pr, tb[besto]);
    } else {
        ce_neg = lse - c.x;
    }
    g_ce[ip] = ce_neg;

    // block reduce via warp shuffles
    #pragma unroll
    for (int off = 16; off; off >>= 1) {
        ll += __shfl_xor_sync(0xffffffffu, ll, off);
        cp += __shfl_xor_sync(0xffffffffu, cp, off);
        np += __shfl_xor_sync(0xffffffffu, np, off);
    }
    __shared__ float wl[8], wc[8];
    __shared__ int   wn[8];
    if (lane == 0) { int w = tid >> 5; wl[w] = ll; wc[w] = cp; wn[w] = np; }
    __syncthreads();
    if (tid == 0) {
        float a = 0.f, cc = 0.f; int nn = 0;
        #pragma unroll
        for (int w = 0; w < 8; w++) { a += wl[w]; cc += wc[w]; nn += wn[w]; }
        int bi = b * gridDim.x + blockIdx.x;
        g_pl[bi] = a; g_pc[bi] = cc; g_pn[bi] = nn;
    }
    if (tid < O) atomicMax(&g_key[b * OMAX + tid], skey[tid]);
}

// ---------------------------------------------------------------------------
// Fixup: one block per batch; forced-match deltas (last-wins on dup priors).
// ---------------------------------------------------------------------------
__global__ __launch_bounds__(128)
void k_fixup(const float* __restrict__ loc,
             const float* __restrict__ conf,
             const float* __restrict__ priors,
             const float* __restrict__ targets,
             int P, int O, int nb) {
    int b   = blockIdx.x;
    int tid = threadIdx.x;
    int lane = tid & 31;

    __shared__ int ps[OMAX];
    __shared__ float rl[4], rc[4];
    __shared__ int   rn[4], rp[4];

    int np = 0;
    for (int j = tid; j < nb; j += 128) np += g_pn[b * nb + j];

    if (tid < O)
        ps[tid] = (int)(~(unsigned int)(g_key[b * OMAX + tid] & 0xffffffffull));
    __syncthreads();

    float dl = 0.0f, dc = 0.0f;
    int dn = 0;

    if (tid < O) {
        int p = ps[tid];
        bool dup = false;
        for (int o2 = tid + 1; o2 < O; o2++) if (ps[o2] == p) dup = true;
        if (!dup) {
            float4 pr = reinterpret_cast<const float4*>(priors)[p];
            float px0 = pr.x - pr.z * 0.5f;
            float py0 = pr.y - pr.w * 0.5f;
            float px1 = pr.x + pr.z * 0.5f;
            float py1 = pr.y + pr.w * 0.5f;
            float pa  = (px1 - px0) * (py1 - py0);

            float best = -1.0f; int bo = 0;
            for (int oo = 0; oo < O; oo++) {
                const float* tt = targets + ((long)b * O + oo) * 5;
                float4 t = make_float4(tt[0], tt[1], tt[2], tt[3]);
                float ta = (t.z - t.x) * (t.w - t.y);
                float iou = iou_one(t, ta, px0, py0, px1, py1, pa);
                if (iou > best) { best = iou; bo = oo; }
            }
            int ct = (best >= OVERLAP_T) ? 1 : 0;

            long ip = (long)b * P + p;
            float4 l = reinterpret_cast<const float4*>(loc)[ip];
            const float* tf = targets + ((long)b * O + tid) * 5;
            float4 tnew = make_float4(tf[0], tf[1], tf[2], tf[3]);
            float sl_new = sl1_of(l, pr, tnew);

            if (ct) {
                const float* to = targets + ((long)b * O + bo) * 5;
                float4 told = make_float4(to[0], to[1], to[2], to[3]);
                dl += sl_new - sl1_of(l, pr, told);
            } else {
                float2 c = reinterpret_cast<const float2*>(conf)[ip];
                float lse = lse2(c);
                dl += sl_new;
                dc += (lse - c.y);
                dn += 1;
                g_ce[ip] = 0.0f;
            }
        }
    }

    #pragma unroll
    for (int off = 16; off; off >>= 1) {
        dl += __shfl_xor_sync(0xffffffffu, dl, off);
        dc += __shfl_xor_sync(0xffffffffu, dc, off);
        dn += __shfl_xor_sync(0xffffffffu, dn, off);
        np += __shfl_xor_sync(0xffffffffu, np, off);
    }
    if (lane == 0) { int w = tid >> 5; rl[w] = dl; rc[w] = dc; rn[w] = dn; rp[w] = np; }
    __syncthreads();
    if (tid == 0) {
        float a = 0.f, cc = 0.f; int nn = 0, pp = 0;
        #pragma unroll
        for (int w = 0; w < 4; w++) { a += rl[w]; cc += rc[w]; nn += rn[w]; pp += rp[w]; }
        g_npos[b] = pp + nn;
        g_fl[b] = a;
        g_fc[b] = cc;
    }
}

// ---------------------------------------------------------------------------
// Top-k sum of negative CE per batch: smem-resident 4-round radix select
// with parallel suffix-scan bin selection, then one strictly-greater sum.
// ---------------------------------------------------------------------------
__global__ __launch_bounds__(1024)
void k_topk(int P) {
    extern __shared__ unsigned int sd[];   // P values, bit-cast floats
    int b    = blockIdx.x;
    int tid  = threadIdx.x;
    int lane = tid & 31;
    const float* v = g_ce + (long)b * P;

    __shared__ unsigned hist[256];
    __shared__ unsigned sfx[256];
    __shared__ unsigned wsum[8];
    __shared__ float    red[32];
    __shared__ int s_krem, s_chosen;
    __shared__ unsigned s_next, s_prefix, s_pmask;

    if (tid == 0) {
        int k = 3 * g_npos[b];
        if (k > P - 1) k = P - 1;
        s_krem = k; s_prefix = 0u; s_pmask = 0u;
    }
    if (tid < 256) hist[tid] = 0u;
    __syncthreads();
    if (s_krem <= 0) { if (tid == 0) g_cneg[b] = 0.0f; return; }

    // Load into smem + round-0 histogram (top byte), warp-aggregated.
    for (int i = tid; i < P; i += 1024) {
        unsigned u = __float_as_uint(v[i]);
        sd[i] = u;
        unsigned bin = u >> 24;
        unsigned grp = __match_any_sync(0xffffffffu, bin);
        if (lane == (int)(__ffs(grp) - 1)) atomicAdd(&hist[bin], (unsigned)__popc(grp));
    }
    __syncthreads();

    for (int r = 0; r < 4; r++) {
        int shift = 24 - 8 * r;
        if (r > 0) {
            if (tid < 256) hist[tid] = 0u;
            __syncthreads();
            unsigned pmask = s_pmask, prefix = s_prefix;
            for (int i = tid; i < P; i += 1024) {
                unsigned u = sd[i];
                if ((u & pmask) == prefix) {
                    unsigned bin = (u >> shift) & 255u;
                    unsigned act = __activemask();
                    unsigned grp = __match_any_sync(act, bin);
                    if (lane == (int)(__ffs(grp) - 1))
                        atomicAdd(&hist[bin], (unsigned)__popc(grp));
                }
            }
            __syncthreads();
        }

        // Parallel suffix sum: sfx[i] = sum_{j>=i} hist[j]
        if (tid < 256) {
            unsigned val = hist[tid];
            #pragma unroll
            for (int off = 1; off < 32; off <<= 1) {
                unsigned t2 = __shfl_down_sync(0xffffffffu, val, off);
                if (lane + off < 32) val += t2;
            }
            sfx[tid] = val;                       // suffix within 32-bin group
            if (lane == 0) wsum[tid >> 5] = val;  // group total
        }
        __syncthreads();
        if (tid < 256) {
            int w = tid >> 5;
            unsigned add = 0;
            #pragma unroll
            for (int j = 0; j < 8; j++) if (j > w) add += wsum[j];
            sfx[tid] += add;
        }
        __syncthreads();
        if (tid < 256) {
            unsigned s  = sfx[tid];
            unsigned sn = (tid < 255) ? sfx[tid + 1] : 0u;
            int krem = s_krem;
            if ((int)s >= krem && (int)sn < krem) { s_chosen = tid; s_next = sn; }
        }
        __syncthreads();
        if (tid == 0) {
            s_krem  -= (int)s_next;
            s_prefix |= ((unsigned)s_chosen << shift);
            s_pmask  |= (255u << shift);
        }
        __syncthreads();
    }

    unsigned tbits = s_prefix;
    float tval = __uint_as_float(tbits);
    float acc = 0.0f;
    for (int i = tid; i < P; i += 1024) {
        unsigned u = sd[i];
        if (u > tbits) acc += __uint_as_float(u);
    }
    #pragma unroll
    for (int off = 16; off; off >>= 1)
        acc += __shfl_xor_sync(0xffffffffu, acc, off);
    if (lane == 0) red[tid >> 5] = acc;
    __syncthreads();
    if (tid < 32) {
        float a = red[tid];
        #pragma unroll
        for (int off = 16; off; off >>= 1)
            a += __shfl_xor_sync(0xffffffffu, a, off);
        if (tid == 0) g_cneg[b] = a + (float)s_krem * tval;
    }
}

// ---------------------------------------------------------------------------
// Final reduction → out[0]=loss_l/N, out[1]=loss_c/N
// ---------------------------------------------------------------------------
__global__ __launch_bounds__(256)
void k_final(float* __restrict__ out, int B, int nb) {
    __shared__ double sl[256], sc[256];
    __shared__ int    sn[256];
    int tid = threadIdx.x;
    double a = 0.0, c2 = 0.0;
    int n = 0;
    int tot = B * nb;
    for (int i = tid; i < tot; i += 256) { a += (double)g_pl[i]; c2 += (double)g_pc[i]; }
    for (int i = tid; i < B; i += 256) {
        a  += (double)g_fl[i];
        c2 += (double)g_fc[i] + (double)g_cneg[i];
        n  += g_npos[i];
    }
    sl[tid] = a; sc[tid] = c2; sn[tid] = n;
    __syncthreads();
    for (int s = 128; s; s >>= 1) {
        if (tid < s) { sl[tid] += sl[tid + s]; sc[tid] += sc[tid + s]; sn[tid] += sn[tid + s]; }
        __syncthreads();
    }
    if (tid == 0) {
        double N = (double)sn[0];
        if (N < 1.0) N = 1.0;
        out[0] = (float)(sl[0] / N);
        out[1] = (float)(sc[0] / N);
    }
}

extern "C" void kernel_launch(void* const* d_in, const int* in_sizes, int n_in,
                              void* d_out, int out_size) {
    const float* loc     = (const float*)d_in[0];
    const float* conf    = (const float*)d_in[1];
    const float* priors  = (const float*)d_in[2];
    const float* targets = (const float*)d_in[3];
    float* out = (float*)d_out;

    int P = in_sizes[2] / 4;
    int B = in_sizes[0] / (P * 4);
    int O = in_sizes[3] / (B * 5);
    int nb = (P + 255) / 256;

    static int smem_set = 0;
    if (!smem_set) {
        cudaFuncSetAttribute(k_topk, cudaFuncAttributeMaxDynamicSharedMemorySize,
                             PMAX * 4 + 1024);
        smem_set = 1;
    }

    k_zero<<<(B * OMAX + 255) / 256, 256>>>(B);

    dim3 grid(nb, B);
    k_main<<<grid, 256>>>(loc, conf, priors, targets, P, O);
    k_fixup<<<B, 128>>>(loc, conf, priors, P == 0 ? loc : targets, P, O, nb);
    k_topk<<<B, 1024, P * 4>>>(P);
    k_final<<<1, 256>>>(out, B, nb);
}

// round 5
// speedup vs baseline: 5.5949x; 1.2162x over previous
#include <cuda_runtime.h>

#define OVERLAP_T 0.5f
#define VAR0 0.1f
#define VAR1 0.2f

#define BMAX 64
#define PMAX 32768
#define OMAX 64
#define NBLK (PMAX/256)
#define BUF1 8192
#define BUF2 1024
// dynamic smem layout (uints): sd[PMAX] | buf1[BUF1] | buf2[BUF2] | hist[2048] | sfx[2048]
#define DSMEM_WORDS (PMAX + BUF1 + BUF2 + 2048 + 2048)

// Scratch (static device arrays; no allocation anywhere)
__device__ float               g_ce[BMAX * PMAX];
__device__ unsigned long long  g_key[BMAX * OMAX];
__device__ int                 g_npos[BMAX];
__device__ float               g_pl[BMAX * NBLK];
__device__ float               g_pc[BMAX * NBLK];
__device__ int                 g_pn[BMAX * NBLK];
__device__ float               g_fl[BMAX];
__device__ float               g_fc[BMAX];
__device__ float               g_cneg[BMAX];
__device__ unsigned            g_done;

__global__ void k_zero(int B) {
    int i = blockIdx.x * blockDim.x + threadIdx.x;
    if (i < B * OMAX) g_key[i] = 0ull;
    if (i == 0)       g_done = 0u;
}

__device__ __forceinline__ float iou_one(float4 t, float ta,
                                         float px0, float py0, float px1, float py1,
                                         float pa) {
    float lx = fmaxf(t.x, px0), ly = fmaxf(t.y, py0);
    float rx = fminf(t.z, px1), ry = fminf(t.w, py1);
    float w = fmaxf(rx - lx, 0.0f), h = fmaxf(ry - ly, 0.0f);
    float inter = w * h;
    float den = ta + pa - inter;
    return __fdividef(inter, den);
}

__device__ __forceinline__ float sl1_of(float4 l, float4 pr, float4 t) {
    float gcx = ((t.x + t.z) * 0.5f - pr.x) / (VAR0 * pr.z);
    float gcy = ((t.y + t.w) * 0.5f - pr.y) / (VAR0 * pr.w);
    float gw  = __logf((t.z - t.x) / pr.z) * (1.0f / VAR1);
    float gh  = __logf((t.w - t.y) / pr.w) * (1.0f / VAR1);
    float d0 = l.x - gcx, d1 = l.y - gcy, d2 = l.z - gw, d3 = l.w - gh;
    float a0 = fabsf(d0), a1 = fabsf(d1), a2 = fabsf(d2), a3 = fabsf(d3);
    float s0 = (a0 < 1.0f) ? 0.5f * d0 * d0 : a0 - 0.5f;
    float s1 = (a1 < 1.0f) ? 0.5f * d1 * d1 : a1 - 0.5f;
    float s2 = (a2 < 1.0f) ? 0.5f * d2 * d2 : a2 - 0.5f;
    float s3 = (a3 < 1.0f) ? 0.5f * d3 * d3 : a3 - 0.5f;
    return (s0 + s1) + (s2 + s3);
}

__device__ __forceinline__ float lse2(float2 c) {
    float mx = fmaxf(c.x, c.y);
    float mn = fminf(c.x, c.y);
    return mx + __logf(1.0f + __expf(mn - mx));
}

// ---------------------------------------------------------------------------
// Fused match + loss with per-truth early-out filter.
// ---------------------------------------------------------------------------
__global__ __launch_bounds__(256)
void k_main(const float* __restrict__ loc,
            const float* __restrict__ conf,
            const float* __restrict__ priors,
            const float* __restrict__ targets,
            int P, int O) {
    int b    = blockIdx.y;
    int tid  = threadIdx.x;
    int lane = tid & 31;
    int p    = blockIdx.x * blockDim.x + tid;

    __shared__ float4 tb[OMAX];
    __shared__ float  ta_s[OMAX];
    __shared__ unsigned long long skey[OMAX];

    if (tid < O) {
        const float* t = targets + ((long)b * O + tid) * 5;
        float4 v = make_float4(t[0], t[1], t[2], t[3]);
        tb[tid]   = v;
        ta_s[tid] = (v.z - v.x) * (v.w - v.y);
        skey[tid] = 0ull;
    }
    __syncthreads();

    float4 pr = reinterpret_cast<const float4*>(priors)[p];
    float px0 = pr.x - pr.z * 0.5f;
    float py0 = pr.y - pr.w * 0.5f;
    float px1 = pr.x + pr.z * 0.5f;
    float py1 = pr.y + pr.w * 0.5f;
    float pa  = (px1 - px0) * (py1 - py0);

    float best = -1.0f;
    int   besto = 0;

    const unsigned* skey_hi = reinterpret_cast<const unsigned*>(skey);

    for (int o = 0; o < O; o++) {
        float iou = iou_one(tb[o], ta_s[o], px0, py0, px1, py1, pa);
        if (iou > best) { best = iou; besto = o; }

        unsigned ib = __float_as_uint(iou);
        if (__any_sync(0xffffffffu, ib >= skey_hi[2 * o + 1])) {
            float m = iou;
            #pragma unroll
            for (int off = 16; off; off >>= 1)
                m = fmaxf(m, __shfl_xor_sync(0xffffffffu, m, off));
            unsigned win = __ballot_sync(0xffffffffu, iou == m);
            if (lane == 0) {
                int src = __ffs(win) - 1;
                unsigned long long key =
                    ((unsigned long long)__float_as_uint(m) << 32) |
                    (unsigned int)(~(unsigned int)(p + src));
                if (key > skey[o]) atomicMax(&skey[o], key);
            }
        }
    }

    long ip = (long)b * P + p;
    int ct = (best >= OVERLAP_T) ? 1 : 0;

    float2 c = reinterpret_cast<const float2*>(conf)[ip];
    float lse = lse2(c);

    float ll = 0.0f, cp = 0.0f, ce_neg;
    int np = 0;
    if (ct) {
        np = 1;
        cp = lse - c.y;
        ce_neg = 0.0f;
        float4 l = reinterpret_cast<const float4*>(loc)[ip];
        ll = sl1_of(l, pr, tb[besto]);
    } else {
        ce_neg = lse - c.x;
    }
    g_ce[ip] = ce_neg;

    #pragma unroll
    for (int off = 16; off; off >>= 1) {
        ll += __shfl_xor_sync(0xffffffffu, ll, off);
        cp += __shfl_xor_sync(0xffffffffu, cp, off);
        np += __shfl_xor_sync(0xffffffffu, np, off);
    }
    __shared__ float wl[8], wc[8];
    __shared__ int   wn[8];
    if (lane == 0) { int w = tid >> 5; wl[w] = ll; wc[w] = cp; wn[w] = np; }
    __syncthreads();
    if (tid == 0) {
        float a = 0.f, cc = 0.f; int nn = 0;
        #pragma unroll
        for (int w = 0; w < 8; w++) { a += wl[w]; cc += wc[w]; nn += wn[w]; }
        int bi = b * gridDim.x + blockIdx.x;
        g_pl[bi] = a; g_pc[bi] = cc; g_pn[bi] = nn;
    }
    if (tid < O) atomicMax(&g_key[b * OMAX + tid], skey[tid]);
}

// ---------------------------------------------------------------------------
// Fused fixup + radix-select top-k + (last block) final reduction.
// All large arrays carved out of dynamic shared memory (static cap is 48KB).
// ---------------------------------------------------------------------------
__global__ __launch_bounds__(1024)
void k_topk(const float* __restrict__ loc,
            const float* __restrict__ conf,
            const float* __restrict__ priors,
            const float* __restrict__ targets,
            float* __restrict__ out,
            int P, int O, int nb, int B) {
    extern __shared__ unsigned dyn[];
    unsigned* sd   = dyn;                 // P staged values
    unsigned* buf1 = dyn + P;             // BUF1
    unsigned* buf2 = buf1 + BUF1;         // BUF2
    unsigned* hist = buf2 + BUF2;         // 2048
    unsigned* sfx  = hist + 2048;         // 2048

    __shared__ unsigned csum[64], cadd[64];
    __shared__ int      ps[OMAX];
    __shared__ float    fred[32];
    __shared__ int      ired[32];
    __shared__ double   dredA[32], dredC[32];
    __shared__ float    s_dl, s_dc;
    __shared__ int      s_dn, s_np, s_krem, s_chosen, s_last;
    __shared__ unsigned s_above, s_cnt1, s_cnt2;

    int b    = blockIdx.x;
    int tid  = threadIdx.x;
    int lane = tid & 31;
    int wrp  = tid >> 5;

    // ---------------- fixup prologue ----------------
    if (tid == 0) { s_dl = 0.f; s_dc = 0.f; s_dn = 0; s_cnt1 = 0u; s_cnt2 = 0u; }
    int np = 0;
    for (int j = tid; j < nb; j += 1024) np += g_pn[b * nb + j];
    #pragma unroll
    for (int off = 16; off; off >>= 1) np += __shfl_xor_sync(0xffffffffu, np, off);
    if (lane == 0) ired[wrp] = np;
    if (tid < O)
        ps[tid] = (int)(~(unsigned int)(g_key[b * OMAX + tid] & 0xffffffffull));
    __syncthreads();
    if (tid == 0) {
        int acc0 = 0;
        #pragma unroll
        for (int w = 0; w < 32; w++) acc0 += ired[w];
        s_np = acc0;
    }

    if (tid < O) {
        int p = ps[tid];
        bool dup = false;
        for (int o2 = tid + 1; o2 < O; o2++) if (ps[o2] == p) dup = true;
        if (!dup) {
            float4 pr = reinterpret_cast<const float4*>(priors)[p];
            float px0 = pr.x - pr.z * 0.5f;
            float py0 = pr.y - pr.w * 0.5f;
            float px1 = pr.x + pr.z * 0.5f;
            float py1 = pr.y + pr.w * 0.5f;
            float pa  = (px1 - px0) * (py1 - py0);

            float best = -1.0f; int bo = 0;
            for (int oo = 0; oo < O; oo++) {
                const float* tt = targets + ((long)b * O + oo) * 5;
                float4 t = make_float4(tt[0], tt[1], tt[2], tt[3]);
                float ta = (t.z - t.x) * (t.w - t.y);
                float iou = iou_one(t, ta, px0, py0, px1, py1, pa);
                if (iou > best) { best = iou; bo = oo; }
            }
            int ct = (best >= OVERLAP_T) ? 1 : 0;

            long ip = (long)b * P + p;
            float4 l = reinterpret_cast<const float4*>(loc)[ip];
            const float* tf = targets + ((long)b * O + tid) * 5;
            float4 tnew = make_float4(tf[0], tf[1], tf[2], tf[3]);
            float sl_new = sl1_of(l, pr, tnew);

            if (ct) {
                const float* to = targets + ((long)b * O + bo) * 5;
                float4 told = make_float4(to[0], to[1], to[2], to[3]);
                atomicAdd(&s_dl, sl_new - sl1_of(l, pr, told));
            } else {
                float2 c = reinterpret_cast<const float2*>(conf)[ip];
                float lse = lse2(c);
                atomicAdd(&s_dl, sl_new);
                atomicAdd(&s_dc, lse - c.y);
                atomicAdd(&s_dn, 1);
                g_ce[ip] = 0.0f;   // ordered before the load pass by __syncthreads
            }
        }
    }
    for (int i = tid; i < 2048; i += 1024) hist[i] = 0u;
    __syncthreads();

    int npos = s_np + s_dn;
    int k = 3 * npos; if (k > P - 1) k = P - 1;
    if (tid == 0) {
        g_npos[b] = npos;
        g_fl[b] = s_dl;
        g_fc[b] = s_dc;
        s_krem = k;
    }
    __syncthreads();

    float acc = 0.0f;
    int c1 = 0, c2 = 0, c3 = 0;

    if (k > 0) {
        const float* v = g_ce + (long)b * P;

        // ---- pass A: load + round-1 histogram (bits[31:21], 2048 bins) ----
        for (int i = tid; i < P; i += 1024) {
            unsigned u = __float_as_uint(v[i]);
            sd[i] = u;
            atomicAdd(&hist[u >> 21], 1u);
        }
        __syncthreads();

        // ---- selection helper: parallel suffix scan + crossing find ----
        #define SELECT_BIN(NBINS)                                               \
        {                                                                       \
            for (int i = tid; i < (NBINS); i += 1024) {                         \
                unsigned val = hist[i];                                         \
                _Pragma("unroll")                                               \
                for (int off = 1; off < 32; off <<= 1) {                        \
                    unsigned t2 = __shfl_down_sync(0xffffffffu, val, off);      \
                    if (lane + off < 32) val += t2;                             \
                }                                                               \
                sfx[i] = val;                                                   \
                if (lane == 0) csum[i >> 5] = val;                              \
            }                                                                   \
            __syncthreads();                                                    \
            int nch = (NBINS) >> 5;                                             \
            if (tid < nch) {                                                    \
                unsigned add = 0;                                               \
                for (int j = tid + 1; j < nch; j++) add += csum[j];             \
                cadd[tid] = add;                                                \
            }                                                                   \
            __syncthreads();                                                    \
            for (int i = tid; i < (NBINS); i += 1024) sfx[i] += cadd[i >> 5];   \
            __syncthreads();                                                    \
            int krem = s_krem;                                                  \
            for (int i = tid; i < (NBINS); i += 1024) {                         \
                unsigned s  = sfx[i];                                           \
                unsigned sn = (i + 1 < (NBINS)) ? sfx[i + 1] : 0u;              \
                if ((int)s >= krem && (int)sn < krem) {                         \
                    s_chosen = i; s_above = sn;                                 \
                }                                                               \
            }                                                                   \
            __syncthreads();                                                    \
            if (tid == 0) s_krem -= (int)s_above;                               \
        }

        SELECT_BIN(2048);
        c1 = s_chosen;
        for (int i = tid; i < 2048; i += 1024) hist[i] = 0u;
        __syncthreads();

        // ---- pass B: accumulate bins>c1, compact bin==c1, round-2 hist ----
        for (int i = tid; i < P; i += 1024) {
            unsigned u = sd[i];
            int bin = (int)(u >> 21);
            if (bin > c1) acc += __uint_as_float(u);
            else if (bin == c1) {
                unsigned pos = atomicAdd(&s_cnt1, 1u);
                if (pos < BUF1) buf1[pos] = u;
                atomicAdd(&hist[(u >> 10) & 0x7FFu], 1u);
            }
        }
        __syncthreads();

        SELECT_BIN(2048);
        c2 = s_chosen;
        unsigned S1 = s_cnt1;
        if (tid < 1024) hist[tid] = 0u;
        __syncthreads();

        // ---- pass C: among survivors, bins2>c2 → acc, ==c2 → compact ----
        if (S1 <= BUF1) {
            for (unsigned i = tid; i < S1; i += 1024) {
                unsigned u = buf1[i];
                int bin2 = (int)((u >> 10) & 0x7FFu);
                if (bin2 > c2) acc += __uint_as_float(u);
                else if (bin2 == c2) {
                    unsigned pos = atomicAdd(&s_cnt2, 1u);
                    if (pos < BUF2) buf2[pos] = u;
                    atomicAdd(&hist[u & 0x3FFu], 1u);
                }
            }
        } else {
            for (int i = tid; i < P; i += 1024) {
                unsigned u = sd[i];
                if ((int)(u >> 21) != c1) continue;
                int bin2 = (int)((u >> 10) & 0x7FFu);
                if (bin2 > c2) acc += __uint_as_float(u);
                else if (bin2 == c2) {
                    unsigned pos = atomicAdd(&s_cnt2, 1u);
                    if (pos < BUF2) buf2[pos] = u;
                    atomicAdd(&hist[u & 0x3FFu], 1u);
                }
            }
        }
        __syncthreads();

        SELECT_BIN(1024);
        c3 = s_chosen;
        unsigned S2 = s_cnt2;
        __syncthreads();

        // ---- pass D: final strictly-greater among exact-tie bin ----
        if (S2 <= BUF2) {
            for (unsigned i = tid; i < S2; i += 1024) {
                unsigned u = buf2[i];
                if ((int)(u & 0x3FFu) > c3) acc += __uint_as_float(u);
            }
        } else {
            for (int i = tid; i < P; i += 1024) {
                unsigned u = sd[i];
                if ((int)(u >> 21) == c1 && (int)((u >> 10) & 0x7FFu) == c2 &&
                    (int)(u & 0x3FFu) > c3)
                    acc += __uint_as_float(u);
            }
        }

        // block reduce acc
        #pragma unroll
        for (int off = 16; off; off >>= 1)
            acc += __shfl_xor_sync(0xffffffffu, acc, off);
        if (lane == 0) fred[wrp] = acc;
        __syncthreads();
        if (tid == 0) {
            float tot = 0.f;
            #pragma unroll
            for (int w = 0; w < 32; w++) tot += fred[w];
            unsigned tbits = ((unsigned)c1 << 21) | ((unsigned)c2 << 10) | (unsigned)c3;
            g_cneg[b] = tot + (float)s_krem * __uint_as_float(tbits);
        }
    } else {
        if (tid == 0) g_cneg[b] = 0.0f;
    }

    // ---------------- last-block final reduction ----------------
    if (tid == 0) {
        __threadfence();
        unsigned old = atomicAdd(&g_done, 1u);
        s_last = (old == (unsigned)(B - 1));
    }
    __syncthreads();
    if (!s_last) return;
    __threadfence();

    double a = 0.0, cc = 0.0;
    int n = 0;
    int tot = B * nb;
    for (int i = tid; i < tot; i += 1024) { a += (double)g_pl[i]; cc += (double)g_pc[i]; }
    for (int i = tid; i < B; i += 1024) {
        a  += (double)g_fl[i];
        cc += (double)g_fc[i] + (double)g_cneg[i];
        n  += g_npos[i];
    }
    #pragma unroll
    for (int off = 16; off; off >>= 1) {
        a  += __shfl_xor_sync(0xffffffffu, a, off);
        cc += __shfl_xor_sync(0xffffffffu, cc, off);
        n  += __shfl_xor_sync(0xffffffffu, n, off);
    }
    if (lane == 0) { dredA[wrp] = a; dredC[wrp] = cc; ired[wrp] = n; }
    __syncthreads();
    if (tid == 0) {
        double ta = 0.0, tc = 0.0; int tn = 0;
        #pragma unroll
        for (int w = 0; w < 32; w++) { ta += dredA[w]; tc += dredC[w]; tn += ired[w]; }
        double N = (double)tn;
        if (N < 1.0) N = 1.0;
        out[0] = (float)(ta / N);
        out[1] = (float)(tc / N);
    }
}

extern "C" void kernel_launch(void* const* d_in, const int* in_sizes, int n_in,
                              void* d_out, int out_size) {
    const float* loc     = (const float*)d_in[0];
    const float* conf    = (const float*)d_in[1];
    const float* priors  = (const float*)d_in[2];
    const float* targets = (const float*)d_in[3];
    float* out = (float*)d_out;

    int P = in_sizes[2] / 4;
    int B = in_sizes[0] / (P * 4);
    int O = in_sizes[3] / (B * 5);
    int nb = (P + 255) / 256;

    static int smem_set = 0;
    if (!smem_set) {
        cudaFuncSetAttribute(k_topk, cudaFuncAttributeMaxDynamicSharedMemorySize,
                             DSMEM_WORDS * 4);
        smem_set = 1;
    }

    k_zero<<<(B * OMAX + 255) / 256, 256>>>(B);

    dim3 grid(nb, B);
    k_main<<<grid, 256>>>(loc, conf, priors, targets, P, O);
    k_topk<<<B, 1024, (P + BUF1 + BUF2 + 2048 + 2048) * 4>>>(
        loc, conf, priors, targets, out, P, O, nb, B);
}